// round 1
// baseline (speedup 1.0000x reference)
#include <cuda_runtime.h>
#include <cuda_bf16.h>

// ---------------------------------------------------------------------------
// GaborSelfAttention: b=32, w=32, h=32, E=64, H=8
//   g[i,j,h,k,l] = u0*dx + u1*dy + u2*dx^2 + u3*dy^2 + u4*dx*dy  (dx=k-i, dy=l-j)
//   P = softmax over (k,l)
//   AH[b,ij,e,h] = sum_kl X[b,kl,e] * P[ij,h,kl]
//   out[b,ij,f]  = sum_{e,h} AH * fc_w[f, e*8+h] + fc_b[f]
// ---------------------------------------------------------------------------

#define WDIM 32
#define HDIM 32
#define EDIM 64
#define HEADS 8
#define BATCH 32
#define KL 1024                    // w*h
#define MROWS 8192                 // w*h*HEADS
#define NCOLS 2048                 // BATCH*EDIM
#define MFEAT 512                  // EDIM*HEADS

// Scratch (static device globals: no allocation allowed)
__device__ float g_u[HEADS][5];
__device__ float g_Xt[KL * NCOLS];            //  8 MB : Xt[kl][b*64+e]
__device__ float g_P[MROWS * KL];             // 32 MB : P[ij*8+h][kl]
__device__ float g_AH[BATCH * KL * MFEAT];    // 64 MB : AH[(b*1024+ij)][h*64+e]
__device__ float g_fcwt[MFEAT * EDIM];        // fcwt[h*64+e][f]

// ---------------------------------------------------------------------------
__global__ void k_u(const float* __restrict__ centers,
                    const float* __restrict__ spreads) {
    int h = threadIdx.x;
    if (h < HEADS) {
        float s00 = spreads[h*4+0], s01 = spreads[h*4+1];
        float s10 = spreads[h*4+2], s11 = spreads[h*4+3];
        float a  = s00*s00 + s01*s01;      // inv_cov[0][0]
        float bb = s00*s10 + s01*s11;      // inv_cov[0][1]
        float c  = s10*s10 + s11*s11;      // inv_cov[1][1]
        float m1 = centers[h*2+0], m2 = centers[h*2+1];
        g_u[h][0] = a*m1 + bb*m2;
        g_u[h][1] = c*m2 + bb*m1;
        g_u[h][2] = -0.5f*a;
        g_u[h][3] = -0.5f*c;
        g_u[h][4] = -bb;
    }
}

// fcwt[(h*64+e)*64 + f] = fc_w[f*512 + e*8 + h]
__global__ void k_prep_w(const float* __restrict__ fc_w) {
    int idx = blockIdx.x * 256 + threadIdx.x;      // 32768
    int f = idx & 63;
    int mp = idx >> 6;              // h*64+e
    int h = mp >> 6, e = mp & 63;
    g_fcwt[idx] = fc_w[f*512 + e*8 + h];
}

// Xt[kl*2048 + b*64 + e] = X[b*65536 + kl*64 + e]
__global__ void k_transpose(const float* __restrict__ X) {
    int idx = blockIdx.x * 256 + threadIdx.x;      // over 524288 float4
    float4 v = ((const float4*)X)[idx];
    int e4 = idx << 2;
    int b  = e4 >> 16;
    int kl = (e4 >> 6) & 1023;
    int e  = e4 & 63;
    *(float4*)&g_Xt[kl*2048 + b*64 + e] = v;
}

// one block per (ij,h) row: exact softmax over 1024 positions
__global__ __launch_bounds__(256) void k_probs() {
    const int rowid = blockIdx.x;          // ij*8 + h
    const int h  = rowid & 7;
    const int ij = rowid >> 3;
    const int i  = ij >> 5, j = ij & 31;
    const float u0 = g_u[h][0], u1 = g_u[h][1], u2 = g_u[h][2];
    const float u3 = g_u[h][3], u4 = g_u[h][4];

    float v[4];
    float m = -1e30f;
#pragma unroll
    for (int t = 0; t < 4; t++) {
        int kl = threadIdx.x + t*256;
        float dx = (float)((kl >> 5) - i);
        float dy = (float)((kl & 31) - j);
        float g = fmaf(fmaf(u2, dx, u0), dx,
                  fmaf(fmaf(u3, dy, u1), dy, u4*dx*dy));
        v[t] = g;
        m = fmaxf(m, g);
    }
    __shared__ float red[8];
#pragma unroll
    for (int o = 16; o > 0; o >>= 1) m = fmaxf(m, __shfl_xor_sync(0xffffffffu, m, o));
    if ((threadIdx.x & 31) == 0) red[threadIdx.x >> 5] = m;
    __syncthreads();
    float mx = fmaxf(fmaxf(fmaxf(red[0], red[1]), fmaxf(red[2], red[3])),
                     fmaxf(fmaxf(red[4], red[5]), fmaxf(red[6], red[7])));
    __syncthreads();

    float s = 0.f;
#pragma unroll
    for (int t = 0; t < 4; t++) { v[t] = __expf(v[t] - mx); s += v[t]; }
#pragma unroll
    for (int o = 16; o > 0; o >>= 1) s += __shfl_xor_sync(0xffffffffu, s, o);
    if ((threadIdx.x & 31) == 0) red[threadIdx.x >> 5] = s;
    __syncthreads();
    float tot = (red[0]+red[1])+(red[2]+red[3])+((red[4]+red[5])+(red[6]+red[7]));
    float inv = 1.0f / tot;

    float* out = g_P + (size_t)rowid * KL;
#pragma unroll
    for (int t = 0; t < 4; t++) out[threadIdx.x + t*256] = v[t] * inv;
}

// ---------------------------------------------------------------------------
// Main GEMM: C[8192 x 2048] = P[8192 x 1024] * Xt[1024 x 2048]
// BM=128 BN=128 BK=16, 256 threads, 8x8 micro-tile.
// K-window skip: an M-tile (128 rows) has a single i; softmax mass with
// |k - i| > 10 is < e^-45 — skip those K-tiles (BK=16 == half a k-row).
// Epilogue writes directly into AH[(b*1024+ij)][h*64+e].
// ---------------------------------------------------------------------------
__global__ __launch_bounds__(256) void k_gemm() {
    __shared__ float As[16][132];   // transposed, padded
    __shared__ float Bs[16][128];

    const int bn = blockIdx.x;         // 0..15
    const int bm = blockIdx.y;         // 0..63
    const int tid = threadIdx.x;
    const int tx = tid & 15, ty = tid >> 4;

    const int i_tile = bm >> 1;        // (bm*128)>>8
    int klo = i_tile - 10; if (klo < 0)  klo = 0;
    int khi = i_tile + 10; if (khi > 31) khi = 31;

    float acc[8][8];
#pragma unroll
    for (int m = 0; m < 8; m++)
#pragma unroll
        for (int n = 0; n < 8; n++) acc[m][n] = 0.f;

    for (int kt = klo*2; kt <= khi*2 + 1; ++kt) {
        const float* Ap = g_P  + (size_t)(bm*128) * 1024 + kt*16;
        const float* Bp = g_Xt + (size_t)(kt*16) * 2048 + bn*128;
#pragma unroll
        for (int q = 0; q < 2; q++) {
            int idx = q*256 + tid;
            int r  = idx >> 2;             // 0..127
            int c4 = (idx & 3) << 2;       // 0,4,8,12
            float4 va = *(const float4*)(Ap + r*1024 + c4);
            As[c4+0][r] = va.x; As[c4+1][r] = va.y;
            As[c4+2][r] = va.z; As[c4+3][r] = va.w;
            int kk = idx >> 5;             // 0..15
            int n4 = (idx & 31) << 2;      // 0..124
            *(float4*)&Bs[kk][n4] = *(const float4*)(Bp + kk*2048 + n4);
        }
        __syncthreads();
#pragma unroll
        for (int k = 0; k < 16; k++) {
            float4 a0 = *(const float4*)&As[k][ty*8];
            float4 a1 = *(const float4*)&As[k][ty*8+4];
            float4 b0 = *(const float4*)&Bs[k][tx*8];
            float4 b1 = *(const float4*)&Bs[k][tx*8+4];
            float av[8] = {a0.x,a0.y,a0.z,a0.w,a1.x,a1.y,a1.z,a1.w};
            float bv[8] = {b0.x,b0.y,b0.z,b0.w,b1.x,b1.y,b1.z,b1.w};
#pragma unroll
            for (int m = 0; m < 8; m++)
#pragma unroll
                for (int n = 0; n < 8; n++)
                    acc[m][n] = fmaf(av[m], bv[n], acc[m][n]);
        }
        __syncthreads();
    }

    // epilogue: row = ij*8+h ; col = b*64+e  ->  AH[(b*1024+ij)*512 + h*64 + e]
#pragma unroll
    for (int m = 0; m < 8; m++) {
        int row = bm*128 + ty*8 + m;
        int ij = row >> 3, h = row & 7;
        size_t base = (size_t)ij*512 + h*64;
#pragma unroll
        for (int n4 = 0; n4 < 8; n4 += 4) {
            int col = bn*128 + tx*8 + n4;
            int b = col >> 6, e = col & 63;
            float4 v = make_float4(acc[m][n4], acc[m][n4+1], acc[m][n4+2], acc[m][n4+3]);
            *(float4*)&g_AH[(size_t)b*524288 + base + e] = v;
        }
    }
}

// ---------------------------------------------------------------------------
// FC GEMM: out[32768 x 64] = AH[32768 x 512] * fcwt[512 x 64] + fc_b
// BM=128 BN=64 BK=32, 256 threads, 8x4 micro-tile.
// ---------------------------------------------------------------------------
__global__ __launch_bounds__(256) void k_fc(const float* __restrict__ fc_b,
                                            float* __restrict__ out) {
    __shared__ float As[32][132];
    __shared__ float Bs[32][64];

    const int bm = blockIdx.x;               // 0..255
    const int tid = threadIdx.x;
    const int tx = tid & 15, ty = tid >> 4;  // tx -> f (4 each), ty -> rows (8 each)

    float acc[8][4];
#pragma unroll
    for (int m = 0; m < 8; m++)
#pragma unroll
        for (int n = 0; n < 4; n++) acc[m][n] = 0.f;

    for (int kt = 0; kt < 16; ++kt) {
        const float* Ap = g_AH + (size_t)(bm*128) * 512 + kt*32;
        const float* Bp = g_fcwt + (size_t)(kt*32) * 64;
#pragma unroll
        for (int q = 0; q < 4; q++) {
            int idx = q*256 + tid;
            int r  = idx >> 3;             // 0..127
            int c4 = (idx & 7) << 2;       // 0..28
            float4 va = *(const float4*)(Ap + r*512 + c4);
            As[c4+0][r] = va.x; As[c4+1][r] = va.y;
            As[c4+2][r] = va.z; As[c4+3][r] = va.w;
        }
#pragma unroll
        for (int q = 0; q < 2; q++) {
            int idx = q*256 + tid;
            int kk = idx >> 4;             // 0..31
            int n4 = (idx & 15) << 2;      // 0..60
            *(float4*)&Bs[kk][n4] = *(const float4*)(Bp + kk*64 + n4);
        }
        __syncthreads();
#pragma unroll
        for (int k = 0; k < 32; k++) {
            float4 a0 = *(const float4*)&As[k][ty*8];
            float4 a1 = *(const float4*)&As[k][ty*8+4];
            float4 b0 = *(const float4*)&Bs[k][tx*4];
            float av[8] = {a0.x,a0.y,a0.z,a0.w,a1.x,a1.y,a1.z,a1.w};
            float bv[4] = {b0.x,b0.y,b0.z,b0.w};
#pragma unroll
            for (int m = 0; m < 8; m++)
#pragma unroll
                for (int n = 0; n < 4; n++)
                    acc[m][n] = fmaf(av[m], bv[n], acc[m][n]);
        }
        __syncthreads();
    }

    float4 bias = *(const float4*)(fc_b + tx*4);
#pragma unroll
    for (int m = 0; m < 8; m++) {
        int row = bm*128 + ty*8 + m;
        float4 v = make_float4(acc[m][0] + bias.x, acc[m][1] + bias.y,
                               acc[m][2] + bias.z, acc[m][3] + bias.w);
        *(float4*)&out[(size_t)row*64 + tx*4] = v;
    }
}

// ---------------------------------------------------------------------------
extern "C" void kernel_launch(void* const* d_in, const int* in_sizes, int n_in,
                              void* d_out, int out_size) {
    const float* X       = (const float*)d_in[0];   // 32*32*32*64
    // d_in[1] = attention_mask (unused by reference)
    const float* centers = (const float*)d_in[2];   // 8*2
    const float* spreads = (const float*)d_in[3];   // 8*2*2
    const float* fc_w    = (const float*)d_in[4];   // 64*512
    const float* fc_b    = (const float*)d_in[5];   // 64
    float* out = (float*)d_out;

    k_u<<<1, 32>>>(centers, spreads);
    k_prep_w<<<128, 256>>>(fc_w);
    k_transpose<<<2048, 256>>>(X);
    k_probs<<<8192, 256>>>();
    dim3 gg(16, 64);
    k_gemm<<<gg, 256>>>();
    k_fc<<<256, 256>>>(fc_b, out);
}

// round 4
// speedup vs baseline: 2.6441x; 2.6441x over previous
#include <cuda_runtime.h>
#include <cuda_fp16.h>
#include <cstdint>

// ---------------------------------------------------------------------------
// GaborSelfAttention, restructured as ONE windowed fp16 HMMA GEMM:
//   out[ij, (b,f)] = sum_{h,kl} P[ij, h*1024+kl] * Y[(h,kl), (b,f)]
//   Y[(h,kl),(b,f)] = sum_e X[b,kl,e] * fc_w[f, e*8+h]    (fp32, exact)
// b=32, w=h=32, E=64, H=8.  M=1024, N=2048, K=8192 (windowed to ~5120).
// ---------------------------------------------------------------------------

__device__ float  g_u[8][5];
__device__ float  g_W2[8 * 64 * 64];        // W2[h][e][f] = fc_w[f,e*8+h]
__device__ __half g_A[1024 * 8192];         // P  [ij][h*1024+kl]        16 MB
__device__ __half g_B[2048 * 8192];         // Y^T[b*64+f][h*1024+kl]    32 MB

// ------------------------------ PTX helpers -------------------------------
__device__ __forceinline__ uint32_t s2u(const void* p) {
    uint32_t a;
    asm("{ .reg .u64 t; cvta.to.shared.u64 t, %1; cvt.u32.u64 %0, t; }"
        : "=r"(a) : "l"(p));
    return a;
}
__device__ __forceinline__ void cpa16(uint32_t dst, const void* src) {
    asm volatile("cp.async.cg.shared.global [%0], [%1], 16;" :: "r"(dst), "l"(src));
}
__device__ __forceinline__ void cpa_commit() {
    asm volatile("cp.async.commit_group;" ::: "memory");
}
template <int N> __device__ __forceinline__ void cpa_wait() {
    asm volatile("cp.async.wait_group %0;" :: "n"(N) : "memory");
}
__device__ __forceinline__ void mma16816(float c[4], const uint32_t a[4],
                                         const uint32_t b[2]) {
    asm volatile(
        "mma.sync.aligned.m16n8k16.row.col.f32.f16.f16.f32 "
        "{%0,%1,%2,%3}, {%4,%5,%6,%7}, {%8,%9}, {%0,%1,%2,%3};"
        : "+f"(c[0]), "+f"(c[1]), "+f"(c[2]), "+f"(c[3])
        : "r"(a[0]), "r"(a[1]), "r"(a[2]), "r"(a[3]), "r"(b[0]), "r"(b[1]));
}

// ------------------------------ small kernels -----------------------------
__global__ void k_u(const float* __restrict__ centers,
                    const float* __restrict__ spreads) {
    int h = threadIdx.x;
    if (h < 8) {
        float s00 = spreads[h*4+0], s01 = spreads[h*4+1];
        float s10 = spreads[h*4+2], s11 = spreads[h*4+3];
        float a  = s00*s00 + s01*s01;
        float bb = s00*s10 + s01*s11;
        float c  = s10*s10 + s11*s11;
        float m1 = centers[h*2+0], m2 = centers[h*2+1];
        g_u[h][0] = a*m1 + bb*m2;
        g_u[h][1] = c*m2 + bb*m1;
        g_u[h][2] = -0.5f*a;
        g_u[h][3] = -0.5f*c;
        g_u[h][4] = -bb;
    }
}

// W2[h][e][f] = fc_w[f*512 + e*8 + h]
__global__ void k_w2(const float* __restrict__ fc_w) {
    int idx = blockIdx.x * 256 + threadIdx.x;     // 32768
    int h = idx >> 12, e = (idx >> 6) & 63, f = idx & 63;
    g_W2[idx] = fc_w[f*512 + e*8 + h];
}

// Y^T: one block per (b, h, kl-tile of 64).  grid = 32*8*16 = 4096.
__global__ __launch_bounds__(256) void k_y(const float* __restrict__ X) {
    __shared__ float Xs[64][65];
    __shared__ float Ws[64][64];
    const int bid = blockIdx.x;
    const int b   = bid >> 7;
    const int h   = (bid >> 4) & 7;
    const int klt = bid & 15;
    const int tid = threadIdx.x;
    const int tx = tid & 15, ty = tid >> 4;

    const float4* xs = (const float4*)(X + (size_t)b*65536 + (size_t)klt*64*64);
#pragma unroll
    for (int q = 0; q < 4; q++) {
        int idx = q*256 + tid;                    // 1024 float4
        float4 v = xs[idx];
        int r = idx >> 4, c = (idx & 15) << 2;
        Xs[r][c] = v.x; Xs[r][c+1] = v.y; Xs[r][c+2] = v.z; Xs[r][c+3] = v.w;
    }
    const float4* ws = (const float4*)(g_W2 + h*4096);
#pragma unroll
    for (int q = 0; q < 4; q++)
        ((float4*)Ws)[q*256 + tid] = ws[q*256 + tid];
    __syncthreads();

    float acc[4][4];
#pragma unroll
    for (int m = 0; m < 4; m++)
#pragma unroll
        for (int n = 0; n < 4; n++) acc[m][n] = 0.f;
#pragma unroll 4
    for (int e = 0; e < 64; e++) {
        float4 w4 = *(const float4*)&Ws[e][tx*4];
        float x0 = Xs[ty*4+0][e], x1 = Xs[ty*4+1][e];
        float x2 = Xs[ty*4+2][e], x3 = Xs[ty*4+3][e];
        acc[0][0] = fmaf(x0, w4.x, acc[0][0]); acc[0][1] = fmaf(x0, w4.y, acc[0][1]);
        acc[0][2] = fmaf(x0, w4.z, acc[0][2]); acc[0][3] = fmaf(x0, w4.w, acc[0][3]);
        acc[1][0] = fmaf(x1, w4.x, acc[1][0]); acc[1][1] = fmaf(x1, w4.y, acc[1][1]);
        acc[1][2] = fmaf(x1, w4.z, acc[1][2]); acc[1][3] = fmaf(x1, w4.w, acc[1][3]);
        acc[2][0] = fmaf(x2, w4.x, acc[2][0]); acc[2][1] = fmaf(x2, w4.y, acc[2][1]);
        acc[2][2] = fmaf(x2, w4.z, acc[2][2]); acc[2][3] = fmaf(x2, w4.w, acc[2][3]);
        acc[3][0] = fmaf(x3, w4.x, acc[3][0]); acc[3][1] = fmaf(x3, w4.y, acc[3][1]);
        acc[3][2] = fmaf(x3, w4.z, acc[3][2]); acc[3][3] = fmaf(x3, w4.w, acc[3][3]);
    }
    // write: row = b*64 + tx*4+n ; col = h*1024 + klt*64 + ty*4 + m
#pragma unroll
    for (int n = 0; n < 4; n++) {
        __half2 h0 = __floats2half2_rn(acc[0][n], acc[1][n]);
        __half2 h1 = __floats2half2_rn(acc[2][n], acc[3][n]);
        uint32_t d0 = *(uint32_t*)&h0;
        uint32_t d1 = *(uint32_t*)&h1;
        size_t off = (size_t)(b*64 + tx*4 + n) * 8192 + h*1024 + klt*64 + ty*4;
        *(uint2*)&g_B[off] = make_uint2(d0, d1);
    }
}

// exact softmax per (ij,h) row, fp16 output.  grid = 8192.
__global__ __launch_bounds__(256) void k_probs() {
    const int rowid = blockIdx.x;          // ij*8 + h
    const int h  = rowid & 7;
    const int ij = rowid >> 3;
    const int i  = ij >> 5, j = ij & 31;
    const float u0 = g_u[h][0], u1 = g_u[h][1], u2 = g_u[h][2];
    const float u3 = g_u[h][3], u4 = g_u[h][4];

    float v[4];
    float m = -1e30f;
#pragma unroll
    for (int t = 0; t < 4; t++) {
        int kl = threadIdx.x + t*256;
        float dx = (float)((kl >> 5) - i);
        float dy = (float)((kl & 31) - j);
        float g = fmaf(fmaf(u2, dx, u0), dx,
                  fmaf(fmaf(u3, dy, u1), dy, u4*dx*dy));
        v[t] = g;
        m = fmaxf(m, g);
    }
    __shared__ float red[8];
#pragma unroll
    for (int o = 16; o > 0; o >>= 1) m = fmaxf(m, __shfl_xor_sync(0xffffffffu, m, o));
    if ((threadIdx.x & 31) == 0) red[threadIdx.x >> 5] = m;
    __syncthreads();
    float mx = fmaxf(fmaxf(fmaxf(red[0], red[1]), fmaxf(red[2], red[3])),
                     fmaxf(fmaxf(red[4], red[5]), fmaxf(red[6], red[7])));
    __syncthreads();

    float s = 0.f;
#pragma unroll
    for (int t = 0; t < 4; t++) { v[t] = __expf(v[t] - mx); s += v[t]; }
#pragma unroll
    for (int o = 16; o > 0; o >>= 1) s += __shfl_xor_sync(0xffffffffu, s, o);
    if ((threadIdx.x & 31) == 0) red[threadIdx.x >> 5] = s;
    __syncthreads();
    float tot = (red[0]+red[1])+(red[2]+red[3])+((red[4]+red[5])+(red[6]+red[7]));
    float inv = 1.0f / tot;

    __half* out = g_A + (size_t)ij * 8192 + h * 1024;
#pragma unroll
    for (int t = 0; t < 4; t++)
        out[threadIdx.x + t*256] = __float2half_rn(v[t] * inv);
}

// ---------------------------------------------------------------------------
// Main GEMM: out[1024 x 2048] = A[1024 x 8192] * B^T (windowed K), fp16 HMMA.
// BM=128 BN=128 BK=64, 256 threads (8 warps, 2x4), 4-stage cp.async pipeline.
// Epilogue: out[b][ij][f] = C[ij][b*64+f] + fc_b[f].
// Smem/stage: A 128x(64+8pad) + B 128x(64+8pad) halves = 36864 B; 4 stages.
// ---------------------------------------------------------------------------
#define STG 36864
__global__ __launch_bounds__(256, 1) void k_gemm(const float* __restrict__ fc_b,
                                                 float* __restrict__ out) {
    extern __shared__ char sm[];
    const uint32_t sbase = s2u(sm);
    const int tid = threadIdx.x, l = tid & 31, wid = tid >> 5;
    const int warp_m = wid >> 2, warp_n = wid & 3;
    const int bn = blockIdx.x, bm = blockIdx.y;

    // k-window for this M-tile (i in [4bm, 4bm+3]); 4bm+11 is odd, klo even.
    int klo = 4*bm - 8; if (klo < 0) klo = 0;
    int khi = 4*bm + 11; if (khi > 31) khi = 31;
    const int npair = (khi - klo + 1) >> 1;
    const int nt = 8 * npair;

    const __half* Ag0 = g_A + (size_t)(bm * 128) * 8192;
    const __half* Bg0 = g_B + (size_t)(bn * 128) * 8192;

    auto load_stage = [&](int buf, int tile) {
        int hh = tile / npair;
        int kp = tile - hh * npair;
        int kcol = hh * 1024 + (klo + kp * 2) * 32;
        uint32_t Ab = sbase + buf * STG;
        uint32_t Bb = Ab + 18432;
        const __half* Ag = Ag0 + kcol;
        const __half* Bg = Bg0 + kcol;
#pragma unroll
        for (int q = 0; q < 4; q++) {
            int idx = q*256 + tid;
            int r = idx >> 3, c = idx & 7;
            cpa16(Ab + r*144 + c*16, Ag + (size_t)r*8192 + c*8);
            cpa16(Bb + r*144 + c*16, Bg + (size_t)r*8192 + c*8);
        }
        cpa_commit();
    };

    float acc[4][4][4];
#pragma unroll
    for (int mi = 0; mi < 4; mi++)
#pragma unroll
        for (int ni = 0; ni < 4; ni++)
#pragma unroll
            for (int q = 0; q < 4; q++) acc[mi][ni][q] = 0.f;

    load_stage(0, 0);
    load_stage(1, 1);
    load_stage(2, 2);

    const int r8 = l >> 2;            // 0..7
    const int kq = (l & 3) * 2;       // 0,2,4,6

    for (int t = 0; t < nt; t++) {
        cpa_wait<2>();
        __syncthreads();
        if (t + 3 < nt) load_stage((t + 3) & 3, t + 3);

        const __half* As = (const __half*)(sm + (t & 3) * STG);
        const __half* Bs = As + 9216;             // 18432 B
#pragma unroll
        for (int ks = 0; ks < 4; ks++) {
            const int k0 = ks*16 + kq;
            uint32_t a[4][4], b[4][2];
#pragma unroll
            for (int mi = 0; mi < 4; mi++) {
                const __half* p = As + (warp_m*64 + mi*16 + r8) * 72 + k0;
                a[mi][0] = *(const uint32_t*)(p);
                a[mi][1] = *(const uint32_t*)(p + 8*72);
                a[mi][2] = *(const uint32_t*)(p + 8);
                a[mi][3] = *(const uint32_t*)(p + 8*72 + 8);
            }
#pragma unroll
            for (int ni = 0; ni < 4; ni++) {
                const __half* p = Bs + (warp_n*32 + ni*8 + r8) * 72 + k0;
                b[ni][0] = *(const uint32_t*)(p);
                b[ni][1] = *(const uint32_t*)(p + 8);
            }
#pragma unroll
            for (int mi = 0; mi < 4; mi++)
#pragma unroll
                for (int ni = 0; ni < 4; ni++)
                    mma16816(acc[mi][ni], a[mi], b[ni]);
        }
        __syncthreads();
    }

    // epilogue
    const int fbase = (warp_n & 1) * 32 + kq;          // f for (ni=0), +ni*8
    const int bidx = bn * 2 + (warp_n >> 1);           // batch index
    float2 bias[4];
#pragma unroll
    for (int ni = 0; ni < 4; ni++)
        bias[ni] = make_float2(fc_b[fbase + ni*8], fc_b[fbase + ni*8 + 1]);

    float* outb = out + (size_t)bidx * 65536;
#pragma unroll
    for (int mi = 0; mi < 4; mi++) {
        int ij0 = bm*128 + warp_m*64 + mi*16 + r8;
#pragma unroll
        for (int ni = 0; ni < 4; ni++) {
            int f = fbase + ni*8;
            *(float2*)&outb[(size_t)ij0 * 64 + f] =
                make_float2(acc[mi][ni][0] + bias[ni].x,
                            acc[mi][ni][1] + bias[ni].y);
            *(float2*)&outb[(size_t)(ij0 + 8) * 64 + f] =
                make_float2(acc[mi][ni][2] + bias[ni].x,
                            acc[mi][ni][3] + bias[ni].y);
        }
    }
}

// ---------------------------------------------------------------------------
extern "C" void kernel_launch(void* const* d_in, const int* in_sizes, int n_in,
                              void* d_out, int out_size) {
    const float* X       = (const float*)d_in[0];
    const float* centers = (const float*)d_in[2];
    const float* spreads = (const float*)d_in[3];
    const float* fc_w    = (const float*)d_in[4];
    const float* fc_b    = (const float*)d_in[5];
    float* out = (float*)d_out;

    cudaFuncSetAttribute(k_gemm, cudaFuncAttributeMaxDynamicSharedMemorySize,
                         4 * STG);

    k_u<<<1, 32>>>(centers, spreads);
    k_w2<<<128, 256>>>(fc_w);
    k_y<<<4096, 256>>>(X);
    k_probs<<<8192, 256>>>();
    dim3 gg(16, 8);
    k_gemm<<<gg, 256, 4 * STG>>>(fc_b, out);
}

// round 5
// speedup vs baseline: 5.1074x; 1.9316x over previous
#include <cuda_runtime.h>
#include <cuda_fp16.h>
#include <cstdint>

// ---------------------------------------------------------------------------
// GaborSelfAttention as ONE windowed fp16 HMMA GEMM:
//   out[ij,(b,f)] = sum_{h,kl} P[ij, h*1024+kl] * Y[(h,kl),(b,f)]
//   Y[(h,kl),(b,f)] = sum_e X[b,kl,e] * fc_w[f, e*8+h]   (fp16 HMMA, fp32 acc)
// b=32, w=h=32, E=64, H=8.  M=1024, N=2048, K=8192 windowed to ~4096.
// ---------------------------------------------------------------------------

__device__ float  g_u[8][5];
__device__ __half g_W2h[8 * 64 * 64];       // W2t[h][f][e]
__device__ __half g_Xh[32 * 1024 * 64];     // X fp16 [b][kl][e]        4 MB
__device__ __half g_A[1024 * 8192];         // P  [ij][h*1024+kl]      16 MB
__device__ __half g_B[2048 * 8192];         // Y^T[b*64+f][h*1024+kl]  32 MB

// ------------------------------ PTX helpers -------------------------------
__device__ __forceinline__ uint32_t s2u(const void* p) {
    uint32_t a;
    asm("{ .reg .u64 t; cvta.to.shared.u64 t, %1; cvt.u32.u64 %0, t; }"
        : "=r"(a) : "l"(p));
    return a;
}
__device__ __forceinline__ void cpa16(uint32_t dst, const void* src) {
    asm volatile("cp.async.cg.shared.global [%0], [%1], 16;" :: "r"(dst), "l"(src));
}
__device__ __forceinline__ void cpa_commit() {
    asm volatile("cp.async.commit_group;" ::: "memory");
}
template <int N> __device__ __forceinline__ void cpa_wait() {
    asm volatile("cp.async.wait_group %0;" :: "n"(N) : "memory");
}
__device__ __forceinline__ void mma16816(float c[4], const uint32_t a[4],
                                         const uint32_t b[2]) {
    asm volatile(
        "mma.sync.aligned.m16n8k16.row.col.f32.f16.f16.f32 "
        "{%0,%1,%2,%3}, {%4,%5,%6,%7}, {%8,%9}, {%0,%1,%2,%3};"
        : "+f"(c[0]), "+f"(c[1]), "+f"(c[2]), "+f"(c[3])
        : "r"(a[0]), "r"(a[1]), "r"(a[2]), "r"(a[3]), "r"(b[0]), "r"(b[1]));
}
__device__ __forceinline__ void ldm4(uint32_t r[4], uint32_t a) {
    asm volatile("ldmatrix.sync.aligned.m8n8.x4.shared.b16 {%0,%1,%2,%3}, [%4];"
        : "=r"(r[0]), "=r"(r[1]), "=r"(r[2]), "=r"(r[3]) : "r"(a));
}
// SW128 xor swizzle on byte offsets of 128B rows (chunk c ^= row&7)
__device__ __forceinline__ uint32_t swz(uint32_t o) { return o ^ ((o >> 3) & 0x70); }

// ------------------------------ small kernels -----------------------------
__global__ void k_u(const float* __restrict__ centers,
                    const float* __restrict__ spreads) {
    int h = threadIdx.x;
    if (h < 8) {
        float s00 = spreads[h*4+0], s01 = spreads[h*4+1];
        float s10 = spreads[h*4+2], s11 = spreads[h*4+3];
        float a  = s00*s00 + s01*s01;
        float bb = s00*s10 + s01*s11;
        float c  = s10*s10 + s11*s11;
        float m1 = centers[h*2+0], m2 = centers[h*2+1];
        g_u[h][0] = a*m1 + bb*m2;
        g_u[h][1] = c*m2 + bb*m1;
        g_u[h][2] = -0.5f*a;
        g_u[h][3] = -0.5f*c;
        g_u[h][4] = -bb;
    }
}

// W2t[h][f][e] = fc_w[f*512 + e*8 + h]  (fp16)
__global__ void k_w2h(const float* __restrict__ fc_w) {
    int idx = blockIdx.x * 256 + threadIdx.x;    // 32768
    int h = idx >> 12, f = (idx >> 6) & 63, e = idx & 63;
    g_W2h[idx] = __float2half_rn(fc_w[f*512 + e*8 + h]);
}

// X -> fp16 (layout unchanged)
__global__ void k_xh(const float* __restrict__ X) {
    int i = blockIdx.x * 256 + threadIdx.x;      // 262144, 8 floats each
    const float4* src = (const float4*)X + (size_t)i * 2;
    float4 v0 = src[0], v1 = src[1];
    __half2 a = __floats2half2_rn(v0.x, v0.y);
    __half2 b = __floats2half2_rn(v0.z, v0.w);
    __half2 c = __floats2half2_rn(v1.x, v1.y);
    __half2 d = __floats2half2_rn(v1.z, v1.w);
    *(uint4*)&g_Xh[(size_t)i * 8] =
        make_uint4(*(uint32_t*)&a, *(uint32_t*)&b, *(uint32_t*)&c, *(uint32_t*)&d);
}

// ---------------------------------------------------------------------------
// Y^T via HMMA: per (b, h, kl-chunk of 256):  [256 kl x 64 e] @ [64 e x 64 f]
// 256 threads = 8 warps, warp tile 32(m) x 64(n).  Transpose epilogue -> Y^T.
// ---------------------------------------------------------------------------
__global__ __launch_bounds__(256) void k_y2() {
    __shared__ __align__(1024) __half buf[256*64 + 64*64];   // 40 KB
    __half* Xs = buf;            // [256 kl][64 e], 128B rows, swizzled
    __half* Ws = buf + 16384;    // [64 f][64 e]
    const int tid = threadIdx.x, l = tid & 31, wid = tid >> 5;
    const int bx = blockIdx.x;               // 0..1023
    const int b = bx >> 5, h = (bx >> 2) & 7, ck = bx & 3;

    const uint32_t xs = s2u(Xs), ws = s2u(Ws);
    const __half* Xg = g_Xh + ((size_t)b*1024 + ck*256) * 64;
#pragma unroll
    for (int q = 0; q < 8; q++) {
        int idx = q*256 + tid;
        int r = idx >> 3, c = idx & 7;
        cpa16(xs + swz(r*128 + c*16), Xg + (size_t)r*64 + c*8);
    }
    const __half* Wg = g_W2h + h*4096;
#pragma unroll
    for (int q = 0; q < 2; q++) {
        int idx = q*256 + tid;
        int r = idx >> 3, c = idx & 7;
        cpa16(ws + swz(r*128 + c*16), Wg + (size_t)r*64 + c*8);
    }
    cpa_commit();
    cpa_wait<0>();
    __syncthreads();

    const int lm_r = (l & 7) + ((l >> 3) & 1) * 8;
    const int lm_c = l >> 4;
    float acc[2][8][4];
#pragma unroll
    for (int mi = 0; mi < 2; mi++)
#pragma unroll
        for (int ni = 0; ni < 8; ni++)
#pragma unroll
            for (int q = 0; q < 4; q++) acc[mi][ni][q] = 0.f;

#pragma unroll
    for (int ks = 0; ks < 4; ks++) {
        const int ch = 2*ks + lm_c;
        uint32_t a[2][4], bq[4][4];
#pragma unroll
        for (int mi = 0; mi < 2; mi++) {
            int row = wid*32 + mi*16 + lm_r;
            ldm4(a[mi], xs + swz(row*128 + ch*16));
        }
#pragma unroll
        for (int nb = 0; nb < 4; nb++) {
            int row = nb*16 + lm_r;
            ldm4(bq[nb], ws + swz(row*128 + ch*16));
        }
#pragma unroll
        for (int mi = 0; mi < 2; mi++)
#pragma unroll
            for (int ni = 0; ni < 8; ni++) {
                uint32_t bb[2] = {bq[ni>>1][ni&1], bq[ni>>1][(ni&1)+2]};
                mma16816(acc[mi][ni], a[mi], bb);
            }
    }
    __syncthreads();

    // transpose stage: T[f][kl] stride 264 halfs
    __half* T = buf;
    const int r8 = l >> 2, kq = (l & 3) * 2;
#pragma unroll
    for (int mi = 0; mi < 2; mi++)
#pragma unroll
        for (int ni = 0; ni < 8; ni++) {
            int m0 = wid*32 + mi*16 + r8;
            int n0 = ni*8 + kq;
            T[n0*264 + m0]         = __float2half_rn(acc[mi][ni][0]);
            T[(n0+1)*264 + m0]     = __float2half_rn(acc[mi][ni][1]);
            T[n0*264 + m0 + 8]     = __float2half_rn(acc[mi][ni][2]);
            T[(n0+1)*264 + m0 + 8] = __float2half_rn(acc[mi][ni][3]);
        }
    __syncthreads();
#pragma unroll
    for (int q = 0; q < 8; q++) {
        int idx = q*256 + tid;
        int f = idx >> 5, mc = idx & 31;
        uint4 v = *(const uint4*)&T[f*264 + mc*8];
        *(uint4*)&g_B[((size_t)b*64 + f)*8192 + h*1024 + ck*256 + mc*8] = v;
    }
}

// exact softmax, one WARP per (ij,h) row.  grid = 1024 x 256.
__global__ __launch_bounds__(256) void k_probs() {
    const int l = threadIdx.x & 31, wid = threadIdx.x >> 5;
    const int rowid = blockIdx.x * 8 + wid;
    const int h = rowid & 7, ij = rowid >> 3;
    const int i = ij >> 5, j = ij & 31;
    const float u0 = g_u[h][0], u1 = g_u[h][1], u2 = g_u[h][2];
    const float u3 = g_u[h][3], u4 = g_u[h][4];
    const float dy0 = (float)((l & 15)*2 - j), dy1 = dy0 + 1.0f;
    const float gy0 = fmaf(u3, dy0, u1) * dy0;
    const float gy1 = fmaf(u3, dy1, u1) * dy1;
    const float cd0 = u4 * dy0, cd1 = u4 * dy1;
    const int kh = l >> 4;

    float e0[16], e1[16];
    float s = 0.f;
#pragma unroll
    for (int t = 0; t < 16; t++) {
        float dx = (float)(2*t + kh - i);
        float ax = fmaf(u2, dx, u0) * dx;
        e0[t] = __expf(ax + fmaf(cd0, dx, gy0));
        e1[t] = __expf(ax + fmaf(cd1, dx, gy1));
        s += e0[t] + e1[t];
    }
#pragma unroll
    for (int o = 16; o > 0; o >>= 1) s += __shfl_xor_sync(0xffffffffu, s, o);
    const float inv = 1.0f / s;

    __half* out = g_A + (size_t)ij*8192 + h*1024 + kh*32 + (l & 15)*2;
#pragma unroll
    for (int t = 0; t < 16; t++) {
        __half2 p = __floats2half2_rn(e0[t]*inv, e1[t]*inv);
        *(__half2*)(out + t*64) = p;
    }
}

// ---------------------------------------------------------------------------
// Main GEMM: out[1024 x 2048] = A * B^T (windowed K), fp16 HMMA + ldmatrix.
// BM=128 BN=128 BK=64, 256 threads (2x4 warps, 64x32 warp tiles), 4 stages.
// Window |k - i| <= 6 per M-tile.  Epilogue: out[b][ij][f] = C + fc_b[f].
// ---------------------------------------------------------------------------
#define STG 32768
__global__ __launch_bounds__(256, 1) void k_gemm(const float* __restrict__ fc_b,
                                                 float* __restrict__ out) {
    extern __shared__ __align__(1024) char sm[];
    const uint32_t sbase = s2u(sm);
    const int tid = threadIdx.x, l = tid & 31, wid = tid >> 5;
    const int warp_m = wid >> 2, warp_n = wid & 3;
    const int bn = blockIdx.x, bm = blockIdx.y;

    int klo = 4*bm - 6; if (klo < 0) klo = 0;
    int khi = 4*bm + 9; if (khi > 31) khi = 31;
    const int npair = (khi - klo + 1) >> 1;   // 5..8, count always even
    const int nt = 8 * npair;

    const __half* Ag0 = g_A + (size_t)(bm*128)*8192 + klo*32;
    const __half* Bg0 = g_B + (size_t)(bn*128)*8192 + klo*32;

    auto load_stage = [&](int buf, int tile) {
        int hh = tile / npair;
        int kp = tile - hh*npair;
        int kcol = hh*1024 + kp*64;
        uint32_t Ab = sbase + buf*STG, Bb = Ab + 16384;
        const __half* Ag = Ag0 + kcol;
        const __half* Bg = Bg0 + kcol;
#pragma unroll
        for (int q = 0; q < 4; q++) {
            int idx = q*256 + tid;
            int r = idx >> 3, c = idx & 7;
            cpa16(Ab + swz(r*128 + c*16), Ag + (size_t)r*8192 + c*8);
            cpa16(Bb + swz(r*128 + c*16), Bg + (size_t)r*8192 + c*8);
        }
        cpa_commit();
    };

    float acc[4][4][4];
#pragma unroll
    for (int mi = 0; mi < 4; mi++)
#pragma unroll
        for (int ni = 0; ni < 4; ni++)
#pragma unroll
            for (int q = 0; q < 4; q++) acc[mi][ni][q] = 0.f;

    load_stage(0, 0); load_stage(1, 1); load_stage(2, 2);

    const int lm_r = (l & 7) + ((l >> 3) & 1) * 8;
    const int lm_c = l >> 4;

    for (int t = 0; t < nt; t++) {
        __syncthreads();                        // compute(t-1) done everywhere
        if (t + 3 < nt) { load_stage((t+3)&3, t+3); cpa_wait<3>(); }
        else if (t + 2 < nt) cpa_wait<2>();
        else if (t + 1 < nt) cpa_wait<1>();
        else                 cpa_wait<0>();
        __syncthreads();                        // stage t visible to all

        const uint32_t Ab = sbase + (t&3)*STG, Bb = Ab + 16384;
#pragma unroll
        for (int ks = 0; ks < 4; ks++) {
            const int ch = 2*ks + lm_c;
            uint32_t a[4][4], bq[2][4];
#pragma unroll
            for (int mi = 0; mi < 4; mi++) {
                int row = warp_m*64 + mi*16 + lm_r;
                ldm4(a[mi], Ab + swz(row*128 + ch*16));
            }
#pragma unroll
            for (int nb = 0; nb < 2; nb++) {
                int row = warp_n*32 + nb*16 + lm_r;
                ldm4(bq[nb], Bb + swz(row*128 + ch*16));
            }
#pragma unroll
            for (int mi = 0; mi < 4; mi++)
#pragma unroll
                for (int ni = 0; ni < 4; ni++) {
                    uint32_t bb[2] = {bq[ni>>1][ni&1], bq[ni>>1][(ni&1)+2]};
                    mma16816(acc[mi][ni], a[mi], bb);
                }
        }
    }

    // epilogue: col = bn*128 + warp_n*32 + ni*8 + kq  ->  (b, f)
    const int r8 = l >> 2, kq = (l & 3) * 2;
    const int fbase = (warp_n & 1) * 32 + kq;
    const int bidx = bn * 2 + (warp_n >> 1);
    float2 bias[4];
#pragma unroll
    for (int ni = 0; ni < 4; ni++)
        bias[ni] = make_float2(fc_b[fbase + ni*8], fc_b[fbase + ni*8 + 1]);

    float* outb = out + (size_t)bidx * 65536;
#pragma unroll
    for (int mi = 0; mi < 4; mi++) {
        int ij0 = bm*128 + warp_m*64 + mi*16 + r8;
#pragma unroll
        for (int ni = 0; ni < 4; ni++) {
            int f = fbase + ni*8;
            *(float2*)&outb[(size_t)ij0 * 64 + f] =
                make_float2(acc[mi][ni][0] + bias[ni].x,
                            acc[mi][ni][1] + bias[ni].y);
            *(float2*)&outb[(size_t)(ij0 + 8) * 64 + f] =
                make_float2(acc[mi][ni][2] + bias[ni].x,
                            acc[mi][ni][3] + bias[ni].y);
        }
    }
}

// ---------------------------------------------------------------------------
extern "C" void kernel_launch(void* const* d_in, const int* in_sizes, int n_in,
                              void* d_out, int out_size) {
    const float* X       = (const float*)d_in[0];
    const float* centers = (const float*)d_in[2];
    const float* spreads = (const float*)d_in[3];
    const float* fc_w    = (const float*)d_in[4];
    const float* fc_b    = (const float*)d_in[5];
    float* out = (float*)d_out;

    cudaFuncSetAttribute(k_gemm, cudaFuncAttributeMaxDynamicSharedMemorySize,
                         4 * STG);

    k_u<<<1, 32>>>(centers, spreads);
    k_w2h<<<128, 256>>>(fc_w);
    k_xh<<<1024, 256>>>(X);
    k_y2<<<1024, 256>>>();
    k_probs<<<1024, 256>>>();
    dim3 gg(16, 8);
    k_gemm<<<gg, 256, 4 * STG>>>(fc_b, out);
}

// round 6
// speedup vs baseline: 6.0748x; 1.1894x over previous
#include <cuda_runtime.h>
#include <cuda_fp16.h>
#include <cstdint>

// ---------------------------------------------------------------------------
// GaborSelfAttention as ONE windowed fp16 HMMA GEMM:
//   out[ij,(b,f)] = sum_{h,kl} P[ij, h*1024+kl] * Y[(h,kl),(b,f)]
//   Y[(h,kl),(b,f)] = sum_e X[b,kl,e] * fc_w[f, e*8+h]   (fp16 HMMA, fp32 acc)
//   P built from 1-D tables: P = exa[dx] * eyb[dy] * exy[dx*dy], window |dx|<=4.
// b=32, w=h=32, E=64, H=8.  M=1024, N=2048, K=8192 windowed to ~3072.
// ---------------------------------------------------------------------------

__device__ float  g_tab[8][520];            // per-head: [0,15) exa  [15,78) eyb  [78,513) exy
__device__ __half g_W2h[8 * 64 * 64];       // W2t[h][f][e]
__device__ __half g_Xh[32 * 1024 * 64];     // X fp16 [b][kl][e]        4 MB
__device__ __half g_A[1024 * 8192];         // P  [ij][h*1024+kl]      16 MB (windowed valid)
__device__ __half g_B[2048 * 8192];         // Y^T[b*64+f][h*1024+kl]  32 MB

// ------------------------------ PTX helpers -------------------------------
__device__ __forceinline__ uint32_t s2u(const void* p) {
    uint32_t a;
    asm("{ .reg .u64 t; cvta.to.shared.u64 t, %1; cvt.u32.u64 %0, t; }"
        : "=r"(a) : "l"(p));
    return a;
}
__device__ __forceinline__ void cpa16(uint32_t dst, const void* src) {
    asm volatile("cp.async.cg.shared.global [%0], [%1], 16;" :: "r"(dst), "l"(src));
}
__device__ __forceinline__ void cpa_commit() {
    asm volatile("cp.async.commit_group;" ::: "memory");
}
template <int N> __device__ __forceinline__ void cpa_wait() {
    asm volatile("cp.async.wait_group %0;" :: "n"(N) : "memory");
}
__device__ __forceinline__ void mma16816(float c[4], const uint32_t a[4],
                                         const uint32_t b[2]) {
    asm volatile(
        "mma.sync.aligned.m16n8k16.row.col.f32.f16.f16.f32 "
        "{%0,%1,%2,%3}, {%4,%5,%6,%7}, {%8,%9}, {%0,%1,%2,%3};"
        : "+f"(c[0]), "+f"(c[1]), "+f"(c[2]), "+f"(c[3])
        : "r"(a[0]), "r"(a[1]), "r"(a[2]), "r"(a[3]), "r"(b[0]), "r"(b[1]));
}
__device__ __forceinline__ void ldm4(uint32_t r[4], uint32_t a) {
    asm volatile("ldmatrix.sync.aligned.m8n8.x4.shared.b16 {%0,%1,%2,%3}, [%4];"
        : "=r"(r[0]), "=r"(r[1]), "=r"(r[2]), "=r"(r[3]) : "r"(a));
}
__device__ __forceinline__ uint32_t swz(uint32_t o) { return o ^ ((o >> 3) & 0x70); }

// ------------------------------ small kernels -----------------------------
// tables per head: exa[dx+7] (|dx|<=7), eyb[dy+31] (|dy|<=31), exy[m+217] (|m|<=217)
__global__ void k_tab(const float* __restrict__ centers,
                      const float* __restrict__ spreads) {
    const int h = blockIdx.x;
    float s00 = spreads[h*4+0], s01 = spreads[h*4+1];
    float s10 = spreads[h*4+2], s11 = spreads[h*4+3];
    float a  = s00*s00 + s01*s01;
    float bb = s00*s10 + s01*s11;
    float c  = s10*s10 + s11*s11;
    float m1 = centers[h*2+0], m2 = centers[h*2+1];
    float u0 = a*m1 + bb*m2;
    float u1 = c*m2 + bb*m1;
    float u2 = -0.5f*a;
    float u3 = -0.5f*c;
    float u4 = -bb;
    for (int t = threadIdx.x; t < 513; t += 256) {
        float v;
        if (t < 15)      { float dx = (float)(t - 7);        v = expf((u0 + u2*dx)*dx); }
        else if (t < 78) { float dy = (float)(t - 15 - 31);  v = expf((u1 + u3*dy)*dy); }
        else             { float m  = (float)(t - 78 - 217); v = expf(u4*m); }
        g_tab[h][t] = v;
    }
}

// W2t[h][f][e] = fc_w[f*512 + e*8 + h]  (fp16)
__global__ void k_w2h(const float* __restrict__ fc_w) {
    int idx = blockIdx.x * 256 + threadIdx.x;    // 32768
    int h = idx >> 12, f = (idx >> 6) & 63, e = idx & 63;
    g_W2h[idx] = __float2half_rn(fc_w[f*512 + e*8 + h]);
}

// X -> fp16 (layout unchanged)
__global__ void k_xh(const float* __restrict__ X) {
    int i = blockIdx.x * 256 + threadIdx.x;      // 262144, 8 floats each
    const float4* src = (const float4*)X + (size_t)i * 2;
    float4 v0 = src[0], v1 = src[1];
    __half2 a = __floats2half2_rn(v0.x, v0.y);
    __half2 b = __floats2half2_rn(v0.z, v0.w);
    __half2 c = __floats2half2_rn(v1.x, v1.y);
    __half2 d = __floats2half2_rn(v1.z, v1.w);
    *(uint4*)&g_Xh[(size_t)i * 8] =
        make_uint4(*(uint32_t*)&a, *(uint32_t*)&b, *(uint32_t*)&c, *(uint32_t*)&d);
}

// ---------------------------------------------------------------------------
// Y^T via HMMA: per (b, h, kl-chunk of 128):  [128 kl x 64 e] @ [64 e x 64 f]
// 256 threads = 8 warps, warp tile 16(m) x 64(n).  Transpose epilogue -> Y^T.
// ---------------------------------------------------------------------------
__global__ __launch_bounds__(256) void k_y2() {
    __shared__ __align__(1024) __half buf[128*64 + 64*64];   // 24 KB
    __half* Xs = buf;            // [128 kl][64 e], 128B rows, swizzled
    __half* Ws = buf + 8192;     // [64 f][64 e]
    const int tid = threadIdx.x, l = tid & 31, wid = tid >> 5;
    const int bx = blockIdx.x;               // 0..2047
    const int b = bx >> 6, h = (bx >> 3) & 7, ck = bx & 7;

    const uint32_t xs = s2u(Xs), ws = s2u(Ws);
    const __half* Xg = g_Xh + ((size_t)b*1024 + ck*128) * 64;
#pragma unroll
    for (int q = 0; q < 4; q++) {
        int idx = q*256 + tid;
        int r = idx >> 3, c = idx & 7;
        cpa16(xs + swz(r*128 + c*16), Xg + (size_t)r*64 + c*8);
    }
    const __half* Wg = g_W2h + h*4096;
#pragma unroll
    for (int q = 0; q < 2; q++) {
        int idx = q*256 + tid;
        int r = idx >> 3, c = idx & 7;
        cpa16(ws + swz(r*128 + c*16), Wg + (size_t)r*64 + c*8);
    }
    cpa_commit();
    cpa_wait<0>();
    __syncthreads();

    const int lm_r = (l & 7) + ((l >> 3) & 1) * 8;
    const int lm_c = l >> 4;
    float acc[8][4];
#pragma unroll
    for (int ni = 0; ni < 8; ni++)
#pragma unroll
        for (int q = 0; q < 4; q++) acc[ni][q] = 0.f;

#pragma unroll
    for (int ks = 0; ks < 4; ks++) {
        const int ch = 2*ks + lm_c;
        uint32_t a[4], bq[4][4];
        {
            int row = wid*16 + lm_r;
            ldm4(a, xs + swz(row*128 + ch*16));
        }
#pragma unroll
        for (int nb = 0; nb < 4; nb++) {
            int row = nb*16 + lm_r;
            ldm4(bq[nb], ws + swz(row*128 + ch*16));
        }
#pragma unroll
        for (int ni = 0; ni < 8; ni++) {
            uint32_t bb[2] = {bq[ni>>1][ni&1], bq[ni>>1][(ni&1)+2]};
            mma16816(acc[ni], a, bb);
        }
    }
    __syncthreads();

    // transpose stage: T[f][kl] stride 136 halfs
    __half* T = buf;
    const int r8 = l >> 2, kq = (l & 3) * 2;
#pragma unroll
    for (int ni = 0; ni < 8; ni++) {
        int m0 = wid*16 + r8;
        int n0 = ni*8 + kq;
        T[n0*136 + m0]         = __float2half_rn(acc[ni][0]);
        T[(n0+1)*136 + m0]     = __float2half_rn(acc[ni][1]);
        T[n0*136 + m0 + 8]     = __float2half_rn(acc[ni][2]);
        T[(n0+1)*136 + m0 + 8] = __float2half_rn(acc[ni][3]);
    }
    __syncthreads();
#pragma unroll
    for (int q = 0; q < 4; q++) {
        int idx = q*256 + tid;
        int f = idx >> 4, mc = idx & 15;
        uint4 v = *(const uint4*)&T[f*136 + mc*8];
        *(uint4*)&g_B[((size_t)b*64 + f)*8192 + h*1024 + ck*128 + mc*8] = v;
    }
}

// ---------------------------------------------------------------------------
// P on GEMM support only, via tables.  grid = 1024 (ij), 8 warps = 8 heads.
// For row ij: k in [klo, khi] = [max(0,(i&~3)-4), min(31,(i&~3)+7)]  (8..12 k's)
// P = exa[dx]*eyb[dy]*exy[dx*dy]; denominator over same support.
// ---------------------------------------------------------------------------
__global__ __launch_bounds__(256) void k_probs() {
    __shared__ float tab[8][520];
    const int tid = threadIdx.x, l = tid & 31, wid = tid >> 5;
#pragma unroll
    for (int q = 0; q < 16; q++) {
        int idx = q*256 + tid;            // 4096 of 4160
        if (idx < 4160) ((float*)tab)[idx] = ((const float*)g_tab)[idx];
    }
    {
        int idx = 16*256 + tid;
        if (idx < 4160) ((float*)tab)[idx] = ((const float*)g_tab)[idx];
    }
    __syncthreads();

    const int ij = blockIdx.x;
    const int i = ij >> 5, j = ij & 31;
    const int klo = max(0, (i & ~3) - 4);
    const int khi = min(31, (i & ~3) + 7);
    const float* th = tab[wid];
    const int dy = l - j;                    // [-31, 31]
    const float ey = th[15 + dy + 31];

    float vals[12];
    float s = 0.f;
#pragma unroll
    for (int t = 0; t < 12; t++) {
        int k = klo + t;
        int dx = min(k - i, 7);              // clamp keeps index valid when k>khi
        float p = (k <= khi) ? th[dx + 7] * ey * th[78 + 217 + dx*dy] : 0.f;
        vals[t] = p;
        s += p;
    }
#pragma unroll
    for (int o = 16; o > 0; o >>= 1) s += __shfl_xor_sync(0xffffffffu, s, o);
    const float inv = 1.0f / s;

    __half* out = g_A + (size_t)ij*8192 + wid*1024 + l;
#pragma unroll
    for (int t = 0; t < 12; t++) {
        int k = klo + t;
        if (k <= khi) out[k*32] = __float2half_rn(vals[t] * inv);
    }
}

// ---------------------------------------------------------------------------
// Main GEMM: out[1024 x 2048] = A * B^T (windowed K), fp16 HMMA + ldmatrix.
// BM=128 BN=128 BK=64, 256 threads (2x4 warps, 64x32 warp tiles), 4 stages.
// Window: k in [4bm-4, 4bm+7] clamped.  Epilogue: out[b][ij][f] = C + fc_b[f].
// ---------------------------------------------------------------------------
#define STG 32768
__global__ __launch_bounds__(256, 1) void k_gemm(const float* __restrict__ fc_b,
                                                 float* __restrict__ out) {
    extern __shared__ __align__(1024) char sm[];
    const uint32_t sbase = s2u(sm);
    const int tid = threadIdx.x, l = tid & 31, wid = tid >> 5;
    const int warp_m = wid >> 2, warp_n = wid & 3;
    const int bn = blockIdx.x, bm = blockIdx.y;

    int klo = 4*bm - 4; if (klo < 0) klo = 0;
    int khi = 4*bm + 7; if (khi > 31) khi = 31;
    const int npair = (khi - klo + 1) >> 1;   // 4 or 6 (width 8 or 12, even)
    const int nt = 8 * npair;

    const __half* Ag0 = g_A + (size_t)(bm*128)*8192 + klo*32;
    const __half* Bg0 = g_B + (size_t)(bn*128)*8192 + klo*32;

    auto load_stage = [&](int buf, int tile) {
        int hh = tile / npair;
        int kp = tile - hh*npair;
        int kcol = hh*1024 + kp*64;
        uint32_t Ab = sbase + buf*STG, Bb = Ab + 16384;
        const __half* Ag = Ag0 + kcol;
        const __half* Bg = Bg0 + kcol;
#pragma unroll
        for (int q = 0; q < 4; q++) {
            int idx = q*256 + tid;
            int r = idx >> 3, c = idx & 7;
            cpa16(Ab + swz(r*128 + c*16), Ag + (size_t)r*8192 + c*8);
            cpa16(Bb + swz(r*128 + c*16), Bg + (size_t)r*8192 + c*8);
        }
        cpa_commit();
    };

    float acc[4][4][4];
#pragma unroll
    for (int mi = 0; mi < 4; mi++)
#pragma unroll
        for (int ni = 0; ni < 4; ni++)
#pragma unroll
            for (int q = 0; q < 4; q++) acc[mi][ni][q] = 0.f;

    load_stage(0, 0); load_stage(1, 1); load_stage(2, 2);

    const int lm_r = (l & 7) + ((l >> 3) & 1) * 8;
    const int lm_c = l >> 4;

    for (int t = 0; t < nt; t++) {
        __syncthreads();                        // compute(t-1) done everywhere
        if (t + 3 < nt) { load_stage((t+3)&3, t+3); cpa_wait<3>(); }
        else if (t + 2 < nt) cpa_wait<2>();
        else if (t + 1 < nt) cpa_wait<1>();
        else                 cpa_wait<0>();
        __syncthreads();                        // stage t visible to all

        const uint32_t Ab = sbase + (t&3)*STG, Bb = Ab + 16384;
#pragma unroll
        for (int ks = 0; ks < 4; ks++) {
            const int ch = 2*ks + lm_c;
            uint32_t a[4][4], bq[2][4];
#pragma unroll
            for (int mi = 0; mi < 4; mi++) {
                int row = warp_m*64 + mi*16 + lm_r;
                ldm4(a[mi], Ab + swz(row*128 + ch*16));
            }
#pragma unroll
            for (int nb = 0; nb < 2; nb++) {
                int row = warp_n*32 + nb*16 + lm_r;
                ldm4(bq[nb], Bb + swz(row*128 + ch*16));
            }
#pragma unroll
            for (int mi = 0; mi < 4; mi++)
#pragma unroll
                for (int ni = 0; ni < 4; ni++) {
                    uint32_t bb[2] = {bq[ni>>1][ni&1], bq[ni>>1][(ni&1)+2]};
                    mma16816(acc[mi][ni], a[mi], bb);
                }
        }
    }

    // epilogue: col = bn*128 + warp_n*32 + ni*8 + kq  ->  (b, f)
    const int r8 = l >> 2, kq = (l & 3) * 2;
    const int fbase = (warp_n & 1) * 32 + kq;
    const int bidx = bn * 2 + (warp_n >> 1);
    float2 bias[4];
#pragma unroll
    for (int ni = 0; ni < 4; ni++)
        bias[ni] = make_float2(fc_b[fbase + ni*8], fc_b[fbase + ni*8 + 1]);

    float* outb = out + (size_t)bidx * 65536;
#pragma unroll
    for (int mi = 0; mi < 4; mi++) {
        int ij0 = bm*128 + warp_m*64 + mi*16 + r8;
#pragma unroll
        for (int ni = 0; ni < 4; ni++) {
            int f = fbase + ni*8;
            *(float2*)&outb[(size_t)ij0 * 64 + f] =
                make_float2(acc[mi][ni][0] + bias[ni].x,
                            acc[mi][ni][1] + bias[ni].y);
            *(float2*)&outb[(size_t)(ij0 + 8) * 64 + f] =
                make_float2(acc[mi][ni][2] + bias[ni].x,
                            acc[mi][ni][3] + bias[ni].y);
        }
    }
}

// ---------------------------------------------------------------------------
extern "C" void kernel_launch(void* const* d_in, const int* in_sizes, int n_in,
                              void* d_out, int out_size) {
    const float* X       = (const float*)d_in[0];
    const float* centers = (const float*)d_in[2];
    const float* spreads = (const float*)d_in[3];
    const float* fc_w    = (const float*)d_in[4];
    const float* fc_b    = (const float*)d_in[5];
    float* out = (float*)d_out;

    cudaFuncSetAttribute(k_gemm, cudaFuncAttributeMaxDynamicSharedMemorySize,
                         4 * STG);

    k_tab<<<8, 256>>>(centers, spreads);
    k_w2h<<<128, 256>>>(fc_w);
    k_xh<<<1024, 256>>>(X);
    k_y2<<<2048, 256>>>();
    k_probs<<<1024, 256>>>();
    dim3 gg(16, 8);
    k_gemm<<<gg, 256, 4 * STG>>>(fc_b, out);
}